// round 17
// baseline (speedup 1.0000x reference)
#include <cuda_runtime.h>
#include <cuda_bf16.h>
#include <cuda_fp16.h>
#include <cstdint>

#define B_    8
#define S_    1029
#define D_    1024
#define H_    16
#define HD_   64
#define M_    (B_*S_)     // 8232
#define MPAD  8320        // 65 * 128
#define NPFX  5
#define SCALE_ 0.125f
#define SVP   1088        // padded key-stride for transposed V

// ---------------------------------------------------------------------------
// Scratch (device globals — no allocation allowed). .bss zero-init.
// ---------------------------------------------------------------------------
__device__ __align__(16) __half g_qh[B_*H_*S_*HD_];     // fp16 Q (rope in place)
__device__ __align__(16) __half g_kh[B_*H_*S_*HD_];     // fp16 K
__device__ __align__(16) __half g_vth[B_*H_*HD_*SVP];   // V^T [b,h,d,s]

__device__ __align__(16) __half g_aohi[MPAD*D_];  // attn out (fp16) [m,n]
__device__ __align__(16) __half g_wthi[4*D_*D_];  // W^T, [w][n][k]

// ---------------------------------------------------------------------------
// mma.sync helpers (portable PTX)
// ---------------------------------------------------------------------------
__device__ __forceinline__ uint32_t smem_u32(const void* p) {
    uint32_t a;
    asm("{ .reg .u64 t; cvta.to.shared.u64 t, %1; cvt.u32.u64 %0, t; }"
        : "=r"(a) : "l"(p));
    return a;
}
__device__ __forceinline__ void ldsm4(uint32_t* r, uint32_t addr) {
    asm volatile("ldmatrix.sync.aligned.m8n8.x4.shared.b16 {%0,%1,%2,%3}, [%4];"
        : "=r"(r[0]), "=r"(r[1]), "=r"(r[2]), "=r"(r[3]) : "r"(addr));
}
__device__ __forceinline__ void mmah16816(float* c, const uint32_t* a,
                                          const uint32_t* b) {
    asm volatile(
        "mma.sync.aligned.m16n8k16.row.col.f32.f16.f16.f32 "
        "{%0,%1,%2,%3}, {%4,%5,%6,%7}, {%8,%9}, {%0,%1,%2,%3};"
        : "+f"(c[0]), "+f"(c[1]), "+f"(c[2]), "+f"(c[3])
        : "r"(a[0]), "r"(a[1]), "r"(a[2]), "r"(a[3]), "r"(b[0]), "r"(b[1]));
}
__device__ __forceinline__ uint32_t packh2(float a, float b) {
    __half2 h = __halves2half2(__float2half_rn(a), __float2half_rn(b));
    return *(uint32_t*)&h;
}

// ---------------------------------------------------------------------------
// Transpose + round all 4 weights (blockIdx.z = widx).
// ---------------------------------------------------------------------------
__global__ void split_w(const float* __restrict__ W0, const float* __restrict__ W1,
                        const float* __restrict__ W2, const float* __restrict__ W3)
{
    __shared__ float t[32][33];
    int widx = blockIdx.z;
    const float* W = (widx == 0) ? W0 : (widx == 1) ? W1 : (widx == 2) ? W2 : W3;
    int n0 = blockIdx.x * 32, k0 = blockIdx.y * 32;
    int tx = threadIdx.x, ty = threadIdx.y;   // 32 x 8
    #pragma unroll
    for (int i = 0; i < 4; i++)
        t[ty + 8*i][tx] = W[(size_t)(k0 + ty + 8*i) * D_ + n0 + tx];
    __syncthreads();
    __half* Hi = g_wthi + (size_t)widx * D_ * D_;
    #pragma unroll
    for (int i = 0; i < 4; i++) {
        float v = t[tx][ty + 8*i];
        Hi[(size_t)(n0 + ty + 8*i) * D_ + k0 + tx] = __float2half_rn(v);
    }
}

// ---------------------------------------------------------------------------
// fp16 tensor-core GEMM. 32 chunks, BK=32, double-buffered 40KB.
// A source: if Ax != nullptr, read fp32 x and convert in the loader
// (bounds-guarded); else read fp16 g_aohi.
// mode 0 -> dst fp32. mode == -1: fused QKV; grid.y spans 24,
// w = by>>3 selects weight & output (1=q fp16, 2=k fp16, 3=V^T fp16).
// ---------------------------------------------------------------------------
#define ASTRIDE 40
#define TILEB (128*ASTRIDE)
#define GEMM_SMEM (2*2*TILEB*2)             // 40960 bytes

__global__ __launch_bounds__(256) void mma_gemm(
    const float* __restrict__ Ax, int widx, const float* __restrict__ bq_,
    const float* __restrict__ bv_, float* __restrict__ dst, int mode)
{
    extern __shared__ __half smg[];         // [2][2][TILEB]: A,B

    const int tid  = threadIdx.x;
    const int lane = tid & 31, wid = tid >> 5;
    const int wm = wid & 1, wn = wid >> 1;
    const int bm = blockIdx.x * 128;

    int bn, emode;
    const float* bias;
    if (mode == -1) {               // fused QKV
        int w = blockIdx.y >> 3;
        bn    = (blockIdx.y & 7) * 128;
        widx  = w;
        emode = 1 + w;              // 1=q, 2=k, 3=v
        bias  = (w == 0) ? bq_ : (w == 2) ? bv_ : nullptr;
    } else {
        bn    = blockIdx.y * 128;
        emode = mode;
        bias  = bq_;
    }

    const __half* Bw = g_wthi + (size_t)widx * D_ * D_;
    const bool fromX = (Ax != nullptr);

    float acc[4][4][4] = {};

    // A-group loader: returns 8 halves packed in a uint4 for rows/cols of A
    // (fp32 source converts + guards; fp16 source is a straight uint4 load).
    // prologue: chunk 0
    #pragma unroll
    for (int it = 0; it < 2; it++) {
        int idx = tid + it * 256;
        int r = idx >> 2, c8 = (idx & 3) * 8;
        uint4 av;
        if (fromX) {
            int m = bm + r;
            if (m < M_) {
                float4 va = *(const float4*)(Ax + (size_t)m * D_ + c8);
                float4 vb = *(const float4*)(Ax + (size_t)m * D_ + c8 + 4);
                av.x = packh2(va.x, va.y); av.y = packh2(va.z, va.w);
                av.z = packh2(vb.x, vb.y); av.w = packh2(vb.z, vb.w);
            } else av = make_uint4(0u, 0u, 0u, 0u);
        } else {
            av = *(const uint4*)(g_aohi + (size_t)(bm + r) * D_ + c8);
        }
        *(uint4*)&smg[0*TILEB + r*ASTRIDE + c8] = av;
        *(uint4*)&smg[1*TILEB + r*ASTRIDE + c8] =
            *(const uint4*)(Bw + (size_t)(bn + r) * D_ + c8);
    }
    __syncthreads();

    const uint32_t smB = smem_u32(smg);
    const uint32_t aOff = (uint32_t)(wm*64 + (lane & 15)) * 80 + (lane >> 4) * 16;
    const uint32_t bOff = (uint32_t)(wn*32 + (lane & 7) + ((lane >> 4) << 3)) * 80
                          + ((lane >> 3) & 1) * 16;
    const uint32_t TB = TILEB * 2;
    const uint32_t BUFB = 2 * TB;

    const int NCH = 32;
    uint4 p[4];
    for (int t = 0; t < NCH; t++) {
        int buf = t & 1;
        if (t + 1 < NCH) {
            int k0 = (t + 1) * 32;
            #pragma unroll
            for (int it = 0; it < 2; it++) {
                int idx = tid + it * 256;
                int r = idx >> 2, c8 = (idx & 3) * 8;
                if (fromX) {
                    int m = bm + r;
                    if (m < M_) {
                        float4 va = *(const float4*)(Ax + (size_t)m * D_ + k0 + c8);
                        float4 vb = *(const float4*)(Ax + (size_t)m * D_ + k0 + c8 + 4);
                        p[it*2].x = packh2(va.x, va.y); p[it*2].y = packh2(va.z, va.w);
                        p[it*2].z = packh2(vb.x, vb.y); p[it*2].w = packh2(vb.z, vb.w);
                    } else p[it*2] = make_uint4(0u, 0u, 0u, 0u);
                } else {
                    p[it*2] = *(const uint4*)(g_aohi + (size_t)(bm + r) * D_ + k0 + c8);
                }
                p[it*2 + 1] = *(const uint4*)(Bw + (size_t)(bn + r) * D_ + k0 + c8);
            }
        }
        uint32_t aB = smB + buf * BUFB;
        uint32_t bB = aB + TB;
        #pragma unroll
        for (int ks = 0; ks < 2; ks++) {
            uint32_t af[4][4], bf[2][4];
            #pragma unroll
            for (int mt = 0; mt < 4; mt++)
                ldsm4(af[mt], aB + aOff + mt * 16 * 80 + ks * 32);
            #pragma unroll
            for (int bt = 0; bt < 2; bt++)
                ldsm4(bf[bt], bB + bOff + bt * 16 * 80 + ks * 32);
            #pragma unroll
            for (int mt = 0; mt < 4; mt++)
                #pragma unroll
                for (int nt = 0; nt < 4; nt++)
                    mmah16816(acc[mt][nt], af[mt], &bf[nt >> 1][(nt & 1) * 2]);
        }
        if (t + 1 < NCH) {
            int nb = buf ^ 1;
            __half* d0 = smg + nb * 2 * TILEB;
            #pragma unroll
            for (int it = 0; it < 2; it++) {
                int idx = tid + it * 256;
                int r = idx >> 2, c8 = (idx & 3) * 8;
                *(uint4*)&d0[0*TILEB + r*ASTRIDE + c8] = p[it*2 + 0];
                *(uint4*)&d0[1*TILEB + r*ASTRIDE + c8] = p[it*2 + 1];
            }
        }
        __syncthreads();
    }

    const int rg = lane >> 2, cp = (lane & 3) * 2;
    #pragma unroll
    for (int mt = 0; mt < 4; mt++) {
        #pragma unroll
        for (int nt = 0; nt < 4; nt++) {
            int n = bn + wn*32 + nt*8 + cp;
            float b0v = bias ? __ldg(bias + n)     : 0.f;
            float b1v = bias ? __ldg(bias + n + 1) : 0.f;
            #pragma unroll
            for (int h2 = 0; h2 < 2; h2++) {
                int m = bm + wm*64 + mt*16 + rg + h2*8;
                if (m >= M_) continue;
                float v0 = acc[mt][nt][h2*2 + 0] + b0v;
                float v1 = acc[mt][nt][h2*2 + 1] + b1v;
                if (emode == 0) {
                    dst[(size_t)m * D_ + n]     = v0;
                    dst[(size_t)m * D_ + n + 1] = v1;
                } else if (emode == 3) {
                    int b = m / S_, s = m % S_;
                    int h = n >> 6, d = n & 63;
                    size_t o = ((size_t)(b * H_ + h) * HD_ + d) * SVP + s;
                    g_vth[o]       = __float2half_rn(v0);
                    g_vth[o + SVP] = __float2half_rn(v1);
                } else {
                    int b = m / S_, s = m % S_;
                    int h = n >> 6, d = n & 63;
                    __half* g = (emode == 1) ? g_qh : g_kh;
                    size_t o = (((size_t)(b * H_ + h)) * S_ + s) * HD_ + d;
                    *(__half2*)&g[o] = __halves2half2(
                        __float2half_rn(v0), __float2half_rn(v1));
                }
            }
        }
    }
}

// ---------------------------------------------------------------------------
// In-place fp16 RoPE (patch tokens) + q-scale.
// ---------------------------------------------------------------------------
__global__ void rope_kernel(const float* __restrict__ cosp,
                            const float* __restrict__ sinp)
{
    const int total = B_*H_*S_*16;
    int i = blockIdx.x * blockDim.x + threadIdx.x;
    if (i >= total) return;
    const bool isQ = (blockIdx.y == 0);
    int d2 = (i & 15) * 2;
    int s  = (i >> 4) % S_;
    int bh = i / (16 * S_);
    __half* Hp = (isQ ? g_qh : g_kh) + ((size_t)bh * S_ + s) * HD_;

    __half2 a = *(__half2*)&Hp[d2];
    __half2 b = *(__half2*)&Hp[d2 + 32];
    float x0 = __half2float(__low2half(a)),  x1 = __half2float(__high2half(a));
    float z0 = __half2float(__low2half(b)),  z1 = __half2float(__high2half(b));
    float y0, y1, w0, w1;
    if (s < NPFX) {
        y0 = x0; y1 = x1; w0 = z0; w1 = z1;
    } else {
        int p = s - NPFX;
        float2 cA = *(const float2*)&cosp[p*HD_ + d2];
        float2 cB = *(const float2*)&cosp[p*HD_ + d2 + 32];
        float2 sA = *(const float2*)&sinp[p*HD_ + d2];
        float2 sB = *(const float2*)&sinp[p*HD_ + d2 + 32];
        y0 = x0*cA.x - z0*sA.x;
        y1 = x1*cA.y - z1*sA.y;
        w0 = z0*cB.x + x0*sB.x;
        w1 = z1*cB.y + x1*sB.y;
    }
    if (isQ) { y0 *= SCALE_; y1 *= SCALE_; w0 *= SCALE_; w1 *= SCALE_; }
    *(__half2*)&Hp[d2]      = __halves2half2(__float2half_rn(y0), __float2half_rn(y1));
    *(__half2*)&Hp[d2 + 32] = __halves2half2(__float2half_rn(w0), __float2half_rn(w1));
}

// ---------------------------------------------------------------------------
// FA2-style tensor-core flash attention (proven R16): 128-q x 64-k tiles,
// 8 warps each owning 16 q rows; P in registers; warp-local softmax.
// ---------------------------------------------------------------------------
#define QST 72
#define ATT_SMEM ((128+64+64)*QST*2)   // 36864

__global__ __launch_bounds__(256) void attn_kernel()
{
    extern __shared__ char smx[];
    __half* Qhi  = (__half*)smx;            // [128][QST]  (q, d)
    __half* Khi  = Qhi + 128*QST;           // [64][QST]   (key, d)
    __half* Vthi = Khi + 64*QST;            // [64][QST]   (d, key)

    const int tid  = threadIdx.x;
    const int lane = tid & 31, wid = tid >> 5;
    const int rg = lane >> 2, cp = (lane & 3) * 2;
    const int bh = blockIdx.y;
    const int m0 = blockIdx.x * 128;
    const __half* qhp = g_qh + (size_t)bh * S_ * HD_;
    const __half* khp = g_kh + (size_t)bh * S_ * HD_;
    const __half* vhp = g_vth + (size_t)bh * HD_ * SVP;

    const uint4 Z4 = make_uint4(0u, 0u, 0u, 0u);
    #pragma unroll
    for (int it = 0; it < 4; it++) {
        int idx = tid + it * 256;
        int r = idx >> 3, c8 = (idx & 7) * 8;
        uint4 vh = Z4;
        if (m0 + r < S_)
            vh = *(const uint4*)(qhp + (size_t)(m0 + r) * HD_ + c8);
        *(uint4*)&Qhi[r*QST + c8] = vh;
    }

    const uint32_t QB = smem_u32(Qhi);
    const uint32_t KB = smem_u32(Khi);
    const uint32_t VB = smem_u32(Vthi);
    const uint32_t aOffQ = (uint32_t)(wid*16 + (lane & 15)) * 144 + (lane >> 4) * 16;
    const uint32_t bOffB = (uint32_t)((lane & 7) + ((lane >> 4) << 3)) * 144
                           + ((lane >> 3) & 1) * 16;

    float oacc[8][4] = {};
    float mr0 = -1e30f, mr1 = -1e30f;
    float lr0 = 0.f,    lr1 = 0.f;

    for (int n0 = 0; n0 < S_; n0 += 64) {
        __syncthreads();
        #pragma unroll
        for (int it = 0; it < 2; it++) {
            int idx = tid + it * 256;
            int r = idx >> 3, c8 = (idx & 7) * 8;
            uint4 vh = Z4;
            if (n0 + r < S_)
                vh = *(const uint4*)(khp + (size_t)(n0 + r) * HD_ + c8);
            *(uint4*)&Khi[r*QST + c8] = vh;
        }
        #pragma unroll
        for (int it = 0; it < 2; it++) {
            int idx = tid + it * 256;
            int d = idx >> 3, k8 = (idx & 7) * 8;
            *(uint4*)&Vthi[d*QST + k8] =
                *(const uint4*)(vhp + (size_t)d * SVP + n0 + k8);
        }
        __syncthreads();

        float sacc[8][4] = {};
        #pragma unroll
        for (int ks = 0; ks < 4; ks++) {
            uint32_t aq[4];
            ldsm4(aq, QB + aOffQ + ks * 32);
            #pragma unroll
            for (int jj = 0; jj < 4; jj++) {
                uint32_t bf[4];
                ldsm4(bf, KB + bOffB + jj * 16 * 144 + ks * 32);
                mmah16816(sacc[2*jj],     aq, &bf[0]);
                mmah16816(sacc[2*jj + 1], aq, &bf[2]);
            }
        }

        float mlo = -1e30f, mhi = -1e30f;
        #pragma unroll
        for (int j = 0; j < 8; j++) {
            bool v0 = (n0 + 8*j + cp)     < S_;
            bool v1 = (n0 + 8*j + cp + 1) < S_;
            if (!v0) { sacc[j][0] = -1e30f; sacc[j][2] = -1e30f; }
            if (!v1) { sacc[j][1] = -1e30f; sacc[j][3] = -1e30f; }
            mlo = fmaxf(mlo, fmaxf(sacc[j][0], sacc[j][1]));
            mhi = fmaxf(mhi, fmaxf(sacc[j][2], sacc[j][3]));
        }
        mlo = fmaxf(mlo, __shfl_xor_sync(0xFFFFFFFFu, mlo, 1));
        mlo = fmaxf(mlo, __shfl_xor_sync(0xFFFFFFFFu, mlo, 2));
        mhi = fmaxf(mhi, __shfl_xor_sync(0xFFFFFFFFu, mhi, 1));
        mhi = fmaxf(mhi, __shfl_xor_sync(0xFFFFFFFFu, mhi, 2));
        float nm0 = fmaxf(mr0, mlo), nm1 = fmaxf(mr1, mhi);
        float al0 = __expf(mr0 - nm0), al1 = __expf(mr1 - nm1);
        mr0 = nm0; mr1 = nm1;

        uint32_t pa[4][4];
        float s0 = 0.f, s1 = 0.f;
        #pragma unroll
        for (int j = 0; j < 8; j++) {
            float e0 = __expf(sacc[j][0] - mr0);
            float e1 = __expf(sacc[j][1] - mr0);
            float e2 = __expf(sacc[j][2] - mr1);
            float e3 = __expf(sacc[j][3] - mr1);
            s0 += e0 + e1;
            s1 += e2 + e3;
            int ks = j >> 1, hf = (j & 1) * 2;
            pa[ks][hf + 0] = packh2(e0, e1);
            pa[ks][hf + 1] = packh2(e2, e3);
        }
        s0 += __shfl_xor_sync(0xFFFFFFFFu, s0, 1);
        s0 += __shfl_xor_sync(0xFFFFFFFFu, s0, 2);
        s1 += __shfl_xor_sync(0xFFFFFFFFu, s1, 1);
        s1 += __shfl_xor_sync(0xFFFFFFFFu, s1, 2);
        lr0 = lr0 * al0 + s0;
        lr1 = lr1 * al1 + s1;

        #pragma unroll
        for (int j = 0; j < 8; j++) {
            oacc[j][0] *= al0; oacc[j][1] *= al0;
            oacc[j][2] *= al1; oacc[j][3] *= al1;
        }
        #pragma unroll
        for (int ks = 0; ks < 4; ks++) {
            #pragma unroll
            for (int jj = 0; jj < 4; jj++) {
                uint32_t bf[4];
                ldsm4(bf, VB + bOffB + jj * 16 * 144 + ks * 32);
                mmah16816(oacc[2*jj],     pa[ks], &bf[0]);
                mmah16816(oacc[2*jj + 1], pa[ks], &bf[2]);
            }
        }
    }

    const int b = bh / H_, h = bh % H_;
    const int q0 = wid*16 + rg;
    const int q1 = q0 + 8;
    const float inv0 = 1.f / lr0;
    const float inv1 = 1.f / lr1;
    #pragma unroll
    for (int j = 0; j < 8; j++) {
        int d0 = 8*j + cp;
        int mA = m0 + q0;
        if (mA < S_) {
            size_t o = ((size_t)b * S_ + mA) * D_ + h * HD_ + d0;
            *(__half2*)&g_aohi[o] = __halves2half2(
                __float2half_rn(oacc[j][0] * inv0),
                __float2half_rn(oacc[j][1] * inv0));
        }
        int mB = m0 + q1;
        if (mB < S_) {
            size_t o = ((size_t)b * S_ + mB) * D_ + h * HD_ + d0;
            *(__half2*)&g_aohi[o] = __halves2half2(
                __float2half_rn(oacc[j][2] * inv1),
                __float2half_rn(oacc[j][3] * inv1));
        }
    }
}

// ---------------------------------------------------------------------------
extern "C" void kernel_launch(void* const* d_in, const int* in_sizes, int n_in,
                              void* d_out, int out_size)
{
    const float* x        = (const float*)d_in[0];
    const float* rope_cos = (const float*)d_in[1];
    const float* rope_sin = (const float*)d_in[2];
    const float* Wq       = (const float*)d_in[3];
    const float* bq       = (const float*)d_in[4];
    const float* Wk       = (const float*)d_in[5];
    const float* Wv       = (const float*)d_in[6];
    const float* bv       = (const float*)d_in[7];
    const float* Wo       = (const float*)d_in[8];
    const float* bo       = (const float*)d_in[9];
    float* out = (float*)d_out;

    cudaFuncSetAttribute(attn_kernel,
        cudaFuncAttributeMaxDynamicSharedMemorySize, ATT_SMEM);
    cudaFuncSetAttribute(mma_gemm,
        cudaFuncAttributeMaxDynamicSharedMemorySize, GEMM_SMEM);

    dim3 wg(32, 32, 4), wb(32, 8);
    split_w<<<wg, wb>>>(Wq, Wk, Wv, Wo);

    // fused QKV projection; A = x fp32, converted in the loader
    dim3 gq(MPAD / 128, 24);
    mma_gemm<<<gq, 256, GEMM_SMEM>>>(x, 0, bq, bv, nullptr, -1);

    int pairs = B_*H_*S_*16;
    dim3 g2((pairs + 255) / 256, 2);
    rope_kernel<<<g2, 256>>>(rope_cos, rope_sin);

    dim3 g3((S_ + 127) / 128, B_*H_);          // 9 x 128
    attn_kernel<<<g3, 256, ATT_SMEM>>>();

    // output projection (A = g_aohi fp16)
    dim3 go(MPAD / 128, D_ / 128);             // 65 x 8
    mma_gemm<<<go, 256, GEMM_SMEM>>>(nullptr, 3, bo, nullptr, out, 0);
}